// round 4
// baseline (speedup 1.0000x reference)
#include <cuda_runtime.h>

#define NREL 8
#define NU   50000
#define ETOT 3400000
typedef long long ll;

__constant__ int c_N[8]       = {50000,50000,10000,10000,10000,10000,10000,10000};
__constant__ int c_edgeoff[8] = {0,800000,1600000,1900000,2200000,2500000,2800000,3100000};
__constant__ int c_dstt[8]    = {1,0,2,3,4,5,6,7};
__constant__ int c_chunkoff[8]= {0,782,1564,1721,1878,2035,2192,2349};

// dynamic (types 0/1) double-buffered; static (types 2-7) single copy
__device__ float g_embD[2][100000*64];
__device__ float g_embS[60000*64];
__device__ float g_ssrc[2][NREL*NU*2];   // [buf][rel][srcnode][k]
__device__ float g_sdstD[2][2*NU*2];     // [buf][rel0/1][node][k]
__device__ float g_sdstS[60000*2];       // [rel2-7 node][k]
__device__ int   g_rowptr[NREL*(NU+1)];
__device__ int   g_counts[NREL*NU];
__device__ int   g_cursor[NREL*NU];
__device__ int   g_isorted[ETOT];

__device__ __forceinline__ float lrelu(float x){ return x > 0.f ? x : 0.2f*x; }
__device__ __forceinline__ float tanh_f(float x){
    float y; asm("tanh.approx.f32 %0, %1;" : "=f"(y) : "f"(x)); return y;
}

// ---------------- setup ----------------
__global__ void k_zero(){
    int i = blockIdx.x*blockDim.x + threadIdx.x;
    if (i < NREL*NU){ g_counts[i]=0; g_cursor[i]=0; }
}

__global__ void k_count_all(const int* __restrict__ u0, const int* __restrict__ u1,
                            const int* __restrict__ u2, const int* __restrict__ u3,
                            const int* __restrict__ u4, const int* __restrict__ u5,
                            const int* __restrict__ u6, const int* __restrict__ u7){
    int t = blockIdx.x*blockDim.x + threadIdx.x;
    if (t >= ETOT) return;
    int rel = 0;
    #pragma unroll
    for (int j=1;j<8;j++) if (t >= c_edgeoff[j]) rel = j;
    const int* up;
    switch (rel){
        case 0: up=u0; break; case 1: up=u1; break; case 2: up=u2; break; case 3: up=u3; break;
        case 4: up=u4; break; case 5: up=u5; break; case 6: up=u6; break; default: up=u7; break;
    }
    atomicAdd(&g_counts[rel*NU + up[t - c_edgeoff[rel]]], 1);
}

__global__ void k_scan(){
    __shared__ int sm[1024];
    int rel = blockIdx.x, t = threadIdx.x;
    const int n = NU, CH = 49;
    int* cnt = g_counts + rel*NU;
    int* rp  = g_rowptr + rel*(NU+1);
    int c0 = t*CH, c1 = min(c0+CH, n);
    int s = 0;
    for (int i=c0;i<c1;i++) s += cnt[i];
    sm[t] = s; __syncthreads();
    for (int off=1; off<1024; off<<=1){
        int v = (t>=off)? sm[t-off] : 0;
        __syncthreads();
        sm[t] += v;
        __syncthreads();
    }
    int run = sm[t] - s;
    for (int i=c0;i<c1;i++){ rp[i]=run; run+=cnt[i]; }
    if (t==0) rp[n] = sm[1023];
}

__global__ void k_scatter_all(const int* __restrict__ u0, const int* __restrict__ u1,
                              const int* __restrict__ u2, const int* __restrict__ u3,
                              const int* __restrict__ u4, const int* __restrict__ u5,
                              const int* __restrict__ u6, const int* __restrict__ u7,
                              const int* __restrict__ i0, const int* __restrict__ i1,
                              const int* __restrict__ i2, const int* __restrict__ i3,
                              const int* __restrict__ i4, const int* __restrict__ i5,
                              const int* __restrict__ i6, const int* __restrict__ i7){
    int t = blockIdx.x*blockDim.x + threadIdx.x;
    if (t >= ETOT) return;
    int rel = 0;
    #pragma unroll
    for (int j=1;j<8;j++) if (t >= c_edgeoff[j]) rel = j;
    const int *up, *ip;
    switch (rel){
        case 0: up=u0; ip=i0; break; case 1: up=u1; ip=i1; break;
        case 2: up=u2; ip=i2; break; case 3: up=u3; ip=i3; break;
        case 4: up=u4; ip=i4; break; case 5: up=u5; ip=i5; break;
        case 6: up=u6; ip=i6; break; default: up=u7; ip=i7; break;
    }
    int e = t - c_edgeoff[rel];
    int uu = up[e];
    int pos = g_rowptr[rel*(NU+1)+uu] + atomicAdd(&g_cursor[rel*NU+uu], 1);
    g_isorted[c_edgeoff[rel] + pos] = ip[e];
}

// initial projection: l2norm(lrelu(emb_t @ Wtk[t][k]))
__global__ void __launch_bounds__(256) k_proj(
    const float* __restrict__ e0, const float* __restrict__ e1,
    const float* __restrict__ e2, const float* __restrict__ e3,
    const float* __restrict__ e4, const float* __restrict__ e5,
    const float* __restrict__ e6, const float* __restrict__ e7,
    const float* __restrict__ Wtk)
{
    __shared__ float sW[4096];
    __shared__ float sE[4096];
    int b = blockIdx.x;
    int t = 0;
    #pragma unroll
    for (int j=1;j<8;j++) if (b >= c_chunkoff[j]) t = j;
    int n0 = (b - c_chunkoff[t]) * 64;
    const float* embp;
    switch (t){
        case 0: embp=e0; break; case 1: embp=e1; break;
        case 2: embp=e2; break; case 3: embp=e3; break;
        case 4: embp=e4; break; case 5: embp=e5; break;
        case 6: embp=e6; break; default: embp=e7; break;
    }
    int Nt = c_N[t], tid = threadIdx.x;
    for (int i=tid;i<4096;i+=256) sW[i] = Wtk[t*4096 + i];
    for (int i=tid;i<4096;i+=256){
        int n = n0 + (i>>6);
        sE[i] = (n < Nt) ? embp[(ll)n*64 + (i&63)] : 0.f;
    }
    __syncthreads();
    int lane = tid&31, w = tid>>5;
    float acc0[8], acc1[8];
    #pragma unroll
    for (int q=0;q<8;q++){ acc0[q]=0.f; acc1[q]=0.f; }
    #pragma unroll 4
    for (int c=0;c<64;c++){
        float w0 = sW[c*32+lane];
        float w1 = sW[2048+c*32+lane];
        #pragma unroll
        for (int q=0;q<8;q++){
            float e = sE[(w*8+q)*64 + c];
            acc0[q] = fmaf(e,w0,acc0[q]);
            acc1[q] = fmaf(e,w1,acc1[q]);
        }
    }
    #pragma unroll
    for (int q=0;q<8;q++){
        int n = n0 + w*8 + q;
        if (n >= Nt) continue;
        float y0 = lrelu(acc0[q]), y1 = lrelu(acc1[q]);
        float s0 = y0*y0, s1 = y1*y1;
        #pragma unroll
        for (int o=16;o;o>>=1){
            s0 += __shfl_xor_sync(0xffffffffu, s0, o);
            s1 += __shfl_xor_sync(0xffffffffu, s1, o);
        }
        float d0 = fmaxf(sqrtf(s0), 1e-12f);
        float d1 = fmaxf(sqrtf(s1), 1e-12f);
        float* dst;
        if (t < 2) dst = &g_embD[0][(t*NU + n)*64];
        else       dst = &g_embS[((t-2)*10000 + n)*64];
        dst[lane]      = y0 / d0;
        dst[32 + lane] = y1 / d1;
    }
}

// initial per-node attention dot halves (gen-0): 560000 warp tasks
__global__ void k_dots0(const float* __restrict__ at){
    int lane = threadIdx.x & 31;
    int gw = (blockIdx.x*blockDim.x + threadIdx.x) >> 5;
    int k = lane >> 4, col = (lane&15)*2;
    float2 e; const float* ap; float* outp;
    if (gw < 400000){                       // src side, all rels
        int rel = gw / NU, n = gw - rel*NU;
        int type = rel ? 1 : 0;
        e = *(const float2*)&g_embD[0][(type*NU+n)*64 + lane*2];
        ap = &at[(rel*2+k)*64 + col];
        outp = &g_ssrc[0][(rel*NU+n)*2 + k];
    } else if (gw < 450000){                // rel0 dst (type1)
        int n = gw - 400000;
        e = *(const float2*)&g_embD[0][(NU+n)*64 + lane*2];
        ap = &at[(0*2+k)*64 + 32 + col];
        outp = &g_sdstD[0][n*2 + k];
    } else if (gw < 500000){                // rel1 dst (type0)
        int n = gw - 450000;
        e = *(const float2*)&g_embD[0][n*64 + lane*2];
        ap = &at[(1*2+k)*64 + 32 + col];
        outp = &g_sdstD[0][NU*2 + n*2 + k];
    } else {                                // rels 2-7 dst (static types)
        int m = gw - 500000;                // 0..59999
        e = *(const float2*)&g_embS[m*64 + lane*2];
        int rel = 2 + m/10000;
        ap = &at[(rel*2+k)*64 + 32 + col];
        outp = &g_sdstS[m*2 + k];
    }
    float p = e.x*__ldg(&ap[0]) + e.y*__ldg(&ap[1]);
    p += __shfl_xor_sync(0xffffffffu, p, 8);
    p += __shfl_xor_sync(0xffffffffu, p, 4);
    p += __shfl_xor_sync(0xffffffffu, p, 2);
    p += __shfl_xor_sync(0xffffffffu, p, 1);
    if ((lane&15) == 0) *outp = p;
}

// ---------------- fully fused iteration ----------------
// warp per source node: for each of its relations: unnormalized-softmax gather
// + z@W + r, accumulate ego update; then l2norm + next-iter dots. Double-buffered.
__global__ void __launch_bounds__(256) k_iter(const float* __restrict__ W,
                                              const float* __restrict__ q,
                                              const float* __restrict__ at,
                                              int cur, int last){
    __shared__ float sW[1024];
    __shared__ int   sIdx[8][32];
    __shared__ float sWt[8][32];
    int tid = threadIdx.x;
    for (int i=tid;i<1024;i+=256) sW[i] = W[i];
    __syncthreads();
    int lane = tid&31, wl = tid>>5;
    int gw = blockIdx.x*8 + wl;          // 0..99999 (interleaved types)
    int t = gw & 1, n = gw >> 1;
    int nxt = cur ^ 1;
    int k = lane >> 4, col = (lane&15)*2, basel = lane & 16;

    float2 e = *(const float2*)&g_embD[cur][(t*NU + n)*64 + lane*2];

    int j0 = t ? 1 : 0, j1 = t ? 8 : 1;
    for (int rel = j0; rel < j1; rel++){
        float2 ss = *(const float2*)&g_ssrc[cur][(rel*NU+n)*2];
        int rb = rel*(NU+1) + n;
        int row = g_rowptr[rb], deg = g_rowptr[rb+1] - row;
        int eb = c_edgeoff[rel] + row;
        const float *de, *sdb;
        if (rel == 0){      de = &g_embD[cur][NU*64]; sdb = &g_sdstD[cur][0]; }
        else if (rel == 1){ de = &g_embD[cur][0];     sdb = &g_sdstD[cur][NU*2]; }
        else {
            int dt = c_dstt[rel];
            de  = &g_embS[(dt-2)*10000*64];
            sdb = &g_sdstS[(dt-2)*10000*2];
        }
        float zx0=0.f, zy0=0.f, zx1=0.f, zy1=0.f, wsum=0.f;
        for (int base = 0; base < deg; base += 32){
            int rem = deg - base;
            int cnt = rem < 32 ? rem : 32;
            int i = 0; float w = 0.f;
            if (lane < cnt){
                i = g_isorted[eb + base + lane];
                float2 sd = *(const float2*)&sdb[i*2];
                float es = 0.5f*(fmaxf(ss.x+sd.x,0.f) + fmaxf(ss.y+sd.y,0.f));
                w = __expf(es);
            }
            sIdx[wl][lane] = i; sWt[wl][lane] = w;
            wsum += w;
            __syncwarp();
            int jj = 0;
            for (; jj+4 <= cnt; jj += 4){
                int i0=sIdx[wl][jj], i1=sIdx[wl][jj+1], i2=sIdx[wl][jj+2], i3=sIdx[wl][jj+3];
                float w0=sWt[wl][jj], w1=sWt[wl][jj+1], w2=sWt[wl][jj+2], w3=sWt[wl][jj+3];
                float2 v0 = *(const float2*)&de[i0*64 + lane*2];
                float2 v1 = *(const float2*)&de[i1*64 + lane*2];
                float2 v2 = *(const float2*)&de[i2*64 + lane*2];
                float2 v3 = *(const float2*)&de[i3*64 + lane*2];
                zx0 = fmaf(w0, v0.x, zx0); zy0 = fmaf(w0, v0.y, zy0);
                zx1 = fmaf(w1, v1.x, zx1); zy1 = fmaf(w1, v1.y, zy1);
                zx0 = fmaf(w2, v2.x, zx0); zy0 = fmaf(w2, v2.y, zy0);
                zx1 = fmaf(w3, v3.x, zx1); zy1 = fmaf(w3, v3.y, zy1);
            }
            for (; jj < cnt; jj++){
                int ii = sIdx[wl][jj]; float ww = sWt[wl][jj];
                float2 v = *(const float2*)&de[ii*64 + lane*2];
                zx0 = fmaf(ww, v.x, zx0); zy0 = fmaf(ww, v.y, zy0);
            }
            __syncwarp();
        }
        #pragma unroll
        for (int o=16;o;o>>=1) wsum += __shfl_xor_sync(0xffffffffu, wsum, o);
        float inv = (deg > 0) ? __fdividef(1.f, wsum) : 0.f;
        float zx = (zx0+zx1)*inv, zy = (zy0+zy1)*inv;

        // transform: o = lrelu(z) @ W (per factor, shuffle matmul)
        float ax = lrelu(zx), ay = lrelu(zy);
        float ox = 0.f, oy = 0.f;
        #pragma unroll
        for (int c=0;c<32;c++){
            float zc = __shfl_sync(0xffffffffu, (c&1)? ay : ax, basel + (c>>1));
            ox = fmaf(zc, sW[c*32+col],   ox);
            oy = fmaf(zc, sW[c*32+col+1], oy);
        }
        // r = softmax_k( tanh(o) . q[rel] )
        float tt = tanh_f(ox)*__ldg(&q[rel*32+col]) + tanh_f(oy)*__ldg(&q[rel*32+col+1]);
        #pragma unroll
        for (int o=8;o;o>>=1) tt += __shfl_xor_sync(0xffffffffu, tt, o);
        float to = __shfl_xor_sync(0xffffffffu, tt, 16);
        float r = __fdividef(1.f, 1.f + __expf(to - tt));
        e.x = fmaf(ox, r, e.x);
        e.y = fmaf(oy, r, e.y);
    }

    // per-factor l2norm
    float s = e.x*e.x + e.y*e.y;
    #pragma unroll
    for (int o=8;o;o>>=1) s += __shfl_xor_sync(0xffffffffu, s, o);
    float dinv = __fdividef(1.f, fmaxf(sqrtf(s), 1e-12f));
    e.x *= dinv; e.y *= dinv;
    *(float2*)&g_embD[nxt][(t*NU + n)*64 + lane*2] = e;

    if (last) return;
    // next-iteration dot halves
    if (t == 0){
        float p0 = e.x*__ldg(&at[k*64+col])          + e.y*__ldg(&at[k*64+col+1]);          // rel0 src
        float p1 = e.x*__ldg(&at[(2+k)*64+32+col])   + e.y*__ldg(&at[(2+k)*64+32+col+1]);   // rel1 dst
        #pragma unroll
        for (int o=8;o;o>>=1){
            p0 += __shfl_xor_sync(0xffffffffu, p0, o);
            p1 += __shfl_xor_sync(0xffffffffu, p1, o);
        }
        if ((lane&15) == 0){
            g_ssrc[nxt][n*2 + k]          = p0;
            g_sdstD[nxt][NU*2 + n*2 + k]  = p1;
        }
    } else {
        float p[8];
        p[0] = e.x*__ldg(&at[k*64+32+col]) + e.y*__ldg(&at[k*64+32+col+1]);                 // rel0 dst
        #pragma unroll
        for (int rl=1; rl<8; rl++)
            p[rl] = e.x*__ldg(&at[(rl*2+k)*64+col]) + e.y*__ldg(&at[(rl*2+k)*64+col+1]);    // src
        #pragma unroll
        for (int rl=0; rl<8; rl++){
            #pragma unroll
            for (int o=8;o;o>>=1) p[rl] += __shfl_xor_sync(0xffffffffu, p[rl], o);
        }
        if ((lane&15) == 0){
            g_sdstD[nxt][n*2 + k] = p[0];
            #pragma unroll
            for (int rl=1; rl<8; rl++) g_ssrc[nxt][(rl*NU+n)*2 + k] = p[rl];
        }
    }
}

__global__ void k_out(float4* __restrict__ out){
    int i = blockIdx.x*blockDim.x + threadIdx.x;
    if (i >= 160000*16) return;
    int row = i >> 4, c = i & 15;
    const float4* src;
    if (row < 100000) src = (const float4*)&g_embD[0][row*64];
    else              src = (const float4*)&g_embS[(row-100000)*64];
    out[i] = src[c];
}

// ---------------- launch ----------------
extern "C" void kernel_launch(void* const* d_in, const int* in_sizes, int n_in,
                              void* d_out, int out_size) {
    const float* emb[8];
    for (int t=0;t<8;t++) emb[t] = (const float*)d_in[t];
    const int* u[8]; const int* ia[8];
    for (int e=0;e<8;e++){
        u[e]  = (const int*)d_in[8 + 2*e];
        ia[e] = (const int*)d_in[9 + 2*e];
    }
    const float* Wtk = (const float*)d_in[24];
    const float* at  = (const float*)d_in[25];
    const float* W   = (const float*)d_in[26];
    const float* q   = (const float*)d_in[27];

    k_zero<<<(NREL*NU + 255)/256, 256>>>();
    k_count_all<<<(ETOT+255)/256, 256>>>(u[0],u[1],u[2],u[3],u[4],u[5],u[6],u[7]);
    k_scan<<<8, 1024>>>();
    k_scatter_all<<<(ETOT+255)/256, 256>>>(u[0],u[1],u[2],u[3],u[4],u[5],u[6],u[7],
                                           ia[0],ia[1],ia[2],ia[3],ia[4],ia[5],ia[6],ia[7]);
    k_proj<<<2506, 256>>>(emb[0],emb[1],emb[2],emb[3],emb[4],emb[5],emb[6],emb[7], Wtk);
    k_dots0<<<70000, 256>>>(at);

    for (int it=0; it<4; it++)
        k_iter<<<12500, 256>>>(W, q, at, it & 1, it == 3);

    k_out<<<(160000*16 + 255)/256, 256>>>((float4*)d_out);
}

// round 5
// speedup vs baseline: 1.3814x; 1.3814x over previous
#include <cuda_runtime.h>

#define NREL 8
#define NU   50000
#define ETOT 3400000
typedef long long ll;

__constant__ int c_N[8]       = {50000,50000,10000,10000,10000,10000,10000,10000};
__constant__ int c_edgeoff[8] = {0,800000,1600000,1900000,2200000,2500000,2800000,3100000};
__constant__ int c_chunkoff[8]= {0,782,1564,1721,1878,2035,2192,2349};

// dynamic (types 0/1) double-buffered; static (types 2-7) single copy
__device__ float g_embD[2][100000*64];
__device__ float g_embS[60000*64];
__device__ float g_ssrc[2][NREL*NU*2];   // [buf][rel][srcnode][k]
__device__ float g_sdstD[2][2*NU*2];     // [buf][rel0/1 slot][node][k]
__device__ float g_sdstS[60000*2];       // [rel2-7 dst node][k]
__device__ int   g_rowptr[NREL*(NU+1)];
__device__ int   g_counts[NREL*NU];
__device__ int   g_cursor[NREL*NU];
__device__ int   g_isorted[ETOT];

__device__ __forceinline__ float lrelu(float x){ return x > 0.f ? x : 0.2f*x; }
__device__ __forceinline__ float tanh_f(float x){
    float y; asm("tanh.approx.f32 %0, %1;" : "=f"(y) : "f"(x)); return y;
}

// ---------------- setup ----------------
__global__ void k_zero(){
    int i = blockIdx.x*blockDim.x + threadIdx.x;
    if (i < NREL*NU){ g_counts[i]=0; g_cursor[i]=0; }
}

__global__ void k_count_all(const int* __restrict__ u0, const int* __restrict__ u1,
                            const int* __restrict__ u2, const int* __restrict__ u3,
                            const int* __restrict__ u4, const int* __restrict__ u5,
                            const int* __restrict__ u6, const int* __restrict__ u7){
    int t = blockIdx.x*blockDim.x + threadIdx.x;
    if (t >= ETOT) return;
    int rel = 0;
    #pragma unroll
    for (int j=1;j<8;j++) if (t >= c_edgeoff[j]) rel = j;
    const int* up;
    switch (rel){
        case 0: up=u0; break; case 1: up=u1; break; case 2: up=u2; break; case 3: up=u3; break;
        case 4: up=u4; break; case 5: up=u5; break; case 6: up=u6; break; default: up=u7; break;
    }
    atomicAdd(&g_counts[rel*NU + up[t - c_edgeoff[rel]]], 1);
}

__global__ void k_scan(){
    __shared__ int sm[1024];
    int rel = blockIdx.x, t = threadIdx.x;
    const int n = NU, CH = 49;
    int* cnt = g_counts + rel*NU;
    int* rp  = g_rowptr + rel*(NU+1);
    int c0 = t*CH, c1 = min(c0+CH, n);
    int s = 0;
    for (int i=c0;i<c1;i++) s += cnt[i];
    sm[t] = s; __syncthreads();
    for (int off=1; off<1024; off<<=1){
        int v = (t>=off)? sm[t-off] : 0;
        __syncthreads();
        sm[t] += v;
        __syncthreads();
    }
    int run = sm[t] - s;
    for (int i=c0;i<c1;i++){ rp[i]=run; run+=cnt[i]; }
    if (t==0) rp[n] = sm[1023];
}

__global__ void k_scatter_all(const int* __restrict__ u0, const int* __restrict__ u1,
                              const int* __restrict__ u2, const int* __restrict__ u3,
                              const int* __restrict__ u4, const int* __restrict__ u5,
                              const int* __restrict__ u6, const int* __restrict__ u7,
                              const int* __restrict__ i0, const int* __restrict__ i1,
                              const int* __restrict__ i2, const int* __restrict__ i3,
                              const int* __restrict__ i4, const int* __restrict__ i5,
                              const int* __restrict__ i6, const int* __restrict__ i7){
    int t = blockIdx.x*blockDim.x + threadIdx.x;
    if (t >= ETOT) return;
    int rel = 0;
    #pragma unroll
    for (int j=1;j<8;j++) if (t >= c_edgeoff[j]) rel = j;
    const int *up, *ip;
    switch (rel){
        case 0: up=u0; ip=i0; break; case 1: up=u1; ip=i1; break;
        case 2: up=u2; ip=i2; break; case 3: up=u3; ip=i3; break;
        case 4: up=u4; ip=i4; break; case 5: up=u5; ip=i5; break;
        case 6: up=u6; ip=i6; break; default: up=u7; ip=i7; break;
    }
    int e = t - c_edgeoff[rel];
    int uu = up[e];
    int pos = g_rowptr[rel*(NU+1)+uu] + atomicAdd(&g_cursor[rel*NU+uu], 1);
    g_isorted[c_edgeoff[rel] + pos] = ip[e];
}

// initial projection: l2norm(lrelu(emb_t @ Wtk[t][k]))
__global__ void __launch_bounds__(256) k_proj(
    const float* __restrict__ e0, const float* __restrict__ e1,
    const float* __restrict__ e2, const float* __restrict__ e3,
    const float* __restrict__ e4, const float* __restrict__ e5,
    const float* __restrict__ e6, const float* __restrict__ e7,
    const float* __restrict__ Wtk)
{
    __shared__ float sW[4096];
    __shared__ float sE[4096];
    int b = blockIdx.x;
    int t = 0;
    #pragma unroll
    for (int j=1;j<8;j++) if (b >= c_chunkoff[j]) t = j;
    int n0 = (b - c_chunkoff[t]) * 64;
    const float* embp;
    switch (t){
        case 0: embp=e0; break; case 1: embp=e1; break;
        case 2: embp=e2; break; case 3: embp=e3; break;
        case 4: embp=e4; break; case 5: embp=e5; break;
        case 6: embp=e6; break; default: embp=e7; break;
    }
    int Nt = c_N[t], tid = threadIdx.x;
    for (int i=tid;i<4096;i+=256) sW[i] = Wtk[t*4096 + i];
    for (int i=tid;i<4096;i+=256){
        int n = n0 + (i>>6);
        sE[i] = (n < Nt) ? embp[(ll)n*64 + (i&63)] : 0.f;
    }
    __syncthreads();
    int lane = tid&31, w = tid>>5;
    float acc0[8], acc1[8];
    #pragma unroll
    for (int q=0;q<8;q++){ acc0[q]=0.f; acc1[q]=0.f; }
    #pragma unroll 4
    for (int c=0;c<64;c++){
        float w0 = sW[c*32+lane];
        float w1 = sW[2048+c*32+lane];
        #pragma unroll
        for (int q=0;q<8;q++){
            float e = sE[(w*8+q)*64 + c];
            acc0[q] = fmaf(e,w0,acc0[q]);
            acc1[q] = fmaf(e,w1,acc1[q]);
        }
    }
    #pragma unroll
    for (int q=0;q<8;q++){
        int n = n0 + w*8 + q;
        if (n >= Nt) continue;
        float y0 = lrelu(acc0[q]), y1 = lrelu(acc1[q]);
        float s0 = y0*y0, s1 = y1*y1;
        #pragma unroll
        for (int o=16;o;o>>=1){
            s0 += __shfl_xor_sync(0xffffffffu, s0, o);
            s1 += __shfl_xor_sync(0xffffffffu, s1, o);
        }
        float d0 = fmaxf(sqrtf(s0), 1e-12f);
        float d1 = fmaxf(sqrtf(s1), 1e-12f);
        float* dst;
        if (t < 2) dst = &g_embD[0][(t*NU + n)*64];
        else       dst = &g_embS[((t-2)*10000 + n)*64];
        dst[lane]      = y0 / d0;
        dst[32 + lane] = y1 / d1;
    }
}

// initial per-node attention dot halves (gen-0)
__global__ void k_dots0(const float* __restrict__ at){
    int lane = threadIdx.x & 31;
    int gw = (blockIdx.x*blockDim.x + threadIdx.x) >> 5;
    int k = lane >> 4, col = (lane&15)*2;
    float2 e; const float* ap; float* outp;
    if (gw < 400000){                       // src side, all rels
        int rel = gw / NU, n = gw - rel*NU;
        int type = rel ? 1 : 0;
        e = *(const float2*)&g_embD[0][(type*NU+n)*64 + lane*2];
        ap = &at[(rel*2+k)*64 + col];
        outp = &g_ssrc[0][(rel*NU+n)*2 + k];
    } else if (gw < 450000){                // rel0 dst (type1)
        int n = gw - 400000;
        e = *(const float2*)&g_embD[0][(NU+n)*64 + lane*2];
        ap = &at[(0*2+k)*64 + 32 + col];
        outp = &g_sdstD[0][n*2 + k];
    } else if (gw < 500000){                // rel1 dst (type0)
        int n = gw - 450000;
        e = *(const float2*)&g_embD[0][n*64 + lane*2];
        ap = &at[(1*2+k)*64 + 32 + col];
        outp = &g_sdstD[0][NU*2 + n*2 + k];
    } else {                                // rels 2-7 dst (static types)
        int m = gw - 500000;                // 0..59999
        e = *(const float2*)&g_embS[m*64 + lane*2];
        int rel = 2 + m/10000;
        ap = &at[(rel*2+k)*64 + 32 + col];
        outp = &g_sdstS[m*2 + k];
    }
    float p = e.x*__ldg(&ap[0]) + e.y*__ldg(&ap[1]);
    p += __shfl_xor_sync(0xffffffffu, p, 8);
    p += __shfl_xor_sync(0xffffffffu, p, 4);
    p += __shfl_xor_sync(0xffffffffu, p, 2);
    p += __shfl_xor_sync(0xffffffffu, p, 1);
    if ((lane&15) == 0) *outp = p;
}

// ---------------- fused iteration: block = node pair, warp = relation ----------------
// warps 0-6: rels 1-7 of type-1 node n -> r*o into smem
// warp 7   : full pipeline for type-0 node n (rel 0)
// warp 0 after sync: finalize type-1 node n
__global__ void __launch_bounds__(256) k_iter(const float* __restrict__ W,
                                              const float* __restrict__ q,
                                              const float* __restrict__ at,
                                              int cur, int last){
    __shared__ float sW[1024];
    __shared__ float sZ[7][64];
    int tid = threadIdx.x;
    for (int i=tid;i<1024;i+=256) sW[i] = W[i];
    __syncthreads();
    int lane = tid&31, wl = tid>>5;
    int n = blockIdx.x;
    int nxt = cur ^ 1;
    int k = lane>>4, col = (lane&15)*2, basel = lane & 16;

    int rel = (wl == 7) ? 0 : (wl + 1);
    const float *de, *sdb;
    if (rel == 0){      de = &g_embD[cur][NU*64]; sdb = &g_sdstD[cur][0]; }
    else if (rel == 1){ de = &g_embD[cur][0];     sdb = &g_sdstD[cur][NU*2]; }
    else {              de = &g_embS[(rel-2)*10000*64]; sdb = &g_sdstS[(rel-2)*10000*2]; }

    float2 ss = *(const float2*)&g_ssrc[cur][(rel*NU+n)*2];
    int rb = rel*(NU+1) + n;
    int row = g_rowptr[rb], deg = g_rowptr[rb+1] - row;
    int eb = c_edgeoff[rel] + row;

    // single-pass unnormalized softmax gather, shfl-broadcast weights
    float zx0=0.f, zy0=0.f, zx1=0.f, zy1=0.f, wsum=0.f;
    for (int base = 0; base < deg; base += 32){
        int cnt = deg - base; if (cnt > 32) cnt = 32;
        int idx = 0; float w = 0.f;
        if (lane < cnt){
            idx = g_isorted[eb + base + lane];
            float2 sd = *(const float2*)&sdb[idx*2];
            float es = 0.5f*(fmaxf(ss.x+sd.x,0.f) + fmaxf(ss.y+sd.y,0.f));
            w = __expf(es);
        }
        wsum += w;
        int jj = 0;
        for (; jj+4 <= cnt; jj += 4){
            int   i0 = __shfl_sync(0xffffffffu, idx, jj);
            int   i1 = __shfl_sync(0xffffffffu, idx, jj+1);
            int   i2 = __shfl_sync(0xffffffffu, idx, jj+2);
            int   i3 = __shfl_sync(0xffffffffu, idx, jj+3);
            float w0 = __shfl_sync(0xffffffffu, w, jj);
            float w1 = __shfl_sync(0xffffffffu, w, jj+1);
            float w2 = __shfl_sync(0xffffffffu, w, jj+2);
            float w3 = __shfl_sync(0xffffffffu, w, jj+3);
            float2 v0 = *(const float2*)&de[i0*64 + lane*2];
            float2 v1 = *(const float2*)&de[i1*64 + lane*2];
            float2 v2 = *(const float2*)&de[i2*64 + lane*2];
            float2 v3 = *(const float2*)&de[i3*64 + lane*2];
            zx0 = fmaf(w0, v0.x, zx0); zy0 = fmaf(w0, v0.y, zy0);
            zx1 = fmaf(w1, v1.x, zx1); zy1 = fmaf(w1, v1.y, zy1);
            zx0 = fmaf(w2, v2.x, zx0); zy0 = fmaf(w2, v2.y, zy0);
            zx1 = fmaf(w3, v3.x, zx1); zy1 = fmaf(w3, v3.y, zy1);
        }
        for (; jj < cnt; jj++){
            int   ii = __shfl_sync(0xffffffffu, idx, jj);
            float ww = __shfl_sync(0xffffffffu, w, jj);
            float2 v = *(const float2*)&de[ii*64 + lane*2];
            zx0 = fmaf(ww, v.x, zx0); zy0 = fmaf(ww, v.y, zy0);
        }
    }
    #pragma unroll
    for (int o=16;o;o>>=1) wsum += __shfl_xor_sync(0xffffffffu, wsum, o);
    float inv = (deg > 0) ? __fdividef(1.f, wsum) : 0.f;
    float ax = lrelu((zx0+zx1)*inv), ay = lrelu((zy0+zy1)*inv);

    // transform: o = lrelu(z) @ W (per factor, shuffle matmul)
    float ox = 0.f, oy = 0.f;
    #pragma unroll
    for (int c=0;c<32;c++){
        float zc = __shfl_sync(0xffffffffu, (c&1)? ay : ax, basel + (c>>1));
        ox = fmaf(zc, sW[c*32+col],   ox);
        oy = fmaf(zc, sW[c*32+col+1], oy);
    }
    // r = softmax_k( tanh(o) . q[rel] )
    float tt = tanh_f(ox)*__ldg(&q[rel*32+col]) + tanh_f(oy)*__ldg(&q[rel*32+col+1]);
    #pragma unroll
    for (int o=8;o;o>>=1) tt += __shfl_xor_sync(0xffffffffu, tt, o);
    float to = __shfl_xor_sync(0xffffffffu, tt, 16);
    float r = __fdividef(1.f, 1.f + __expf(to - tt));

    if (wl < 7){
        sZ[wl][lane*2]   = r*ox;
        sZ[wl][lane*2+1] = r*oy;
    } else {
        // finalize type-0 node n
        float2 e = *(const float2*)&g_embD[cur][n*64 + lane*2];
        e.x = fmaf(ox, r, e.x);
        e.y = fmaf(oy, r, e.y);
        float s = e.x*e.x + e.y*e.y;
        #pragma unroll
        for (int o=8;o;o>>=1) s += __shfl_xor_sync(0xffffffffu, s, o);
        float dinv = __fdividef(1.f, fmaxf(sqrtf(s), 1e-12f));
        e.x *= dinv; e.y *= dinv;
        *(float2*)&g_embD[nxt][n*64 + lane*2] = e;
        if (!last){
            float p0 = e.x*__ldg(&at[k*64+col])        + e.y*__ldg(&at[k*64+col+1]);        // rel0 src
            float p1 = e.x*__ldg(&at[(2+k)*64+32+col]) + e.y*__ldg(&at[(2+k)*64+32+col+1]); // rel1 dst
            #pragma unroll
            for (int o=8;o;o>>=1){
                p0 += __shfl_xor_sync(0xffffffffu, p0, o);
                p1 += __shfl_xor_sync(0xffffffffu, p1, o);
            }
            if ((lane&15) == 0){
                g_ssrc[nxt][n*2 + k]         = p0;
                g_sdstD[nxt][NU*2 + n*2 + k] = p1;
            }
        }
    }
    __syncthreads();
    if (wl == 0){
        // finalize type-1 node n: ego + sum of rel 1..7 contributions (in rel order)
        float2 e = *(const float2*)&g_embD[cur][(NU+n)*64 + lane*2];
        #pragma unroll
        for (int j=0;j<7;j++){
            e.x += sZ[j][lane*2];
            e.y += sZ[j][lane*2+1];
        }
        float s = e.x*e.x + e.y*e.y;
        #pragma unroll
        for (int o=8;o;o>>=1) s += __shfl_xor_sync(0xffffffffu, s, o);
        float dinv = __fdividef(1.f, fmaxf(sqrtf(s), 1e-12f));
        e.x *= dinv; e.y *= dinv;
        *(float2*)&g_embD[nxt][(NU+n)*64 + lane*2] = e;
        if (!last){
            float p[8];
            p[0] = e.x*__ldg(&at[k*64+32+col]) + e.y*__ldg(&at[k*64+32+col+1]);             // rel0 dst
            #pragma unroll
            for (int rl=1; rl<8; rl++)
                p[rl] = e.x*__ldg(&at[(rl*2+k)*64+col]) + e.y*__ldg(&at[(rl*2+k)*64+col+1]); // src
            #pragma unroll
            for (int rl=0; rl<8; rl++){
                #pragma unroll
                for (int o=8;o;o>>=1) p[rl] += __shfl_xor_sync(0xffffffffu, p[rl], o);
            }
            if ((lane&15) == 0){
                g_sdstD[nxt][n*2 + k] = p[0];
                #pragma unroll
                for (int rl=1; rl<8; rl++) g_ssrc[nxt][(rl*NU+n)*2 + k] = p[rl];
            }
        }
    }
}

__global__ void k_out(float4* __restrict__ out){
    int i = blockIdx.x*blockDim.x + threadIdx.x;
    if (i >= 160000*16) return;
    int row = i >> 4, c = i & 15;
    const float4* src;
    if (row < 100000) src = (const float4*)&g_embD[0][row*64];
    else              src = (const float4*)&g_embS[(ll)(row-100000)*64];
    out[i] = src[c];
}

// ---------------- launch ----------------
extern "C" void kernel_launch(void* const* d_in, const int* in_sizes, int n_in,
                              void* d_out, int out_size) {
    const float* emb[8];
    for (int t=0;t<8;t++) emb[t] = (const float*)d_in[t];
    const int* u[8]; const int* ia[8];
    for (int e=0;e<8;e++){
        u[e]  = (const int*)d_in[8 + 2*e];
        ia[e] = (const int*)d_in[9 + 2*e];
    }
    const float* Wtk = (const float*)d_in[24];
    const float* at  = (const float*)d_in[25];
    const float* W   = (const float*)d_in[26];
    const float* q   = (const float*)d_in[27];

    k_zero<<<(NREL*NU + 255)/256, 256>>>();
    k_count_all<<<(ETOT+255)/256, 256>>>(u[0],u[1],u[2],u[3],u[4],u[5],u[6],u[7]);
    k_scan<<<8, 1024>>>();
    k_scatter_all<<<(ETOT+255)/256, 256>>>(u[0],u[1],u[2],u[3],u[4],u[5],u[6],u[7],
                                           ia[0],ia[1],ia[2],ia[3],ia[4],ia[5],ia[6],ia[7]);
    k_proj<<<2506, 256>>>(emb[0],emb[1],emb[2],emb[3],emb[4],emb[5],emb[6],emb[7], Wtk);
    k_dots0<<<70000, 256>>>(at);

    for (int it=0; it<4; it++)
        k_iter<<<50000, 256>>>(W, q, at, it & 1, it == 3);

    k_out<<<(160000*16 + 255)/256, 256>>>((float4*)d_out);
}